// round 1
// baseline (speedup 1.0000x reference)
#include <cuda_runtime.h>
#include <cstdint>

#define N_TOK   4096
#define C_DIM   64
#define HW      256
#define E_EXP   16
#define CCAP    384
#define PLANE   (E_EXP * CCAP)            /* 6144  */
#define HALF    ((long long)N_TOK * PLANE) /* 25,165,824 */

// ---------------- device scratch (no allocations allowed) ----------------
__device__ float g_gate[N_TOK];
__device__ int   g_arg[N_TOK];
__device__ int   g_pos[N_TOK];
__device__ float g_sump[E_EXP];   // sum of probs per expert
__device__ float g_cnt[E_EXP];    // argmax counts per expert
__device__ float g_zsum;          // sum of logsumexp

// ---------------- kernel 1: zero-fill output + accumulators ----------------
__global__ void k_zero(float* __restrict__ out, long long n4) {
    float4 z = make_float4(0.f, 0.f, 0.f, 0.f);
    float4* o4 = reinterpret_cast<float4*>(out);
    long long stride = (long long)gridDim.x * blockDim.x;
    for (long long i = (long long)blockIdx.x * blockDim.x + threadIdx.x; i < n4; i += stride)
        o4[i] = z;
    if (blockIdx.x == 0) {
        int t = threadIdx.x;
        if (t < E_EXP) { g_sump[t] = 0.f; g_cnt[t] = 0.f; }
        if (t == E_EXP) g_zsum = 0.f;
    }
}

// ---------------- kernel 2: pool + gate + softmax/argmax + loss sums -------
// 1 block per token, 512 threads (16 warps). Warp w owns channels [4w, 4w+4).
__global__ void __launch_bounds__(512, 2)
k_pool(const float* __restrict__ X, const float* __restrict__ Wg,
       const float* __restrict__ bg) {
    __shared__ float s_ch[C_DIM];       // pooled means
    __shared__ float s_w[C_DIM * E_EXP];

    const int n    = blockIdx.x;
    const int tid  = threadIdx.x;
    const int w    = tid >> 5;
    const int lane = tid & 31;

    // stage W_gate in shared (4 KB)
    for (int i = tid; i < C_DIM * E_EXP; i += 512) s_w[i] = Wg[i];

    // coalesced read of this token's 16384 floats as float4
    const float4* xp = reinterpret_cast<const float4*>(X + (size_t)n * C_DIM * HW);
    const float4* p  = xp + w * 256;    // this warp's 4-channel region
    float part[4] = {0.f, 0.f, 0.f, 0.f};
#pragma unroll
    for (int k = 0; k < 8; k++) {
        float4 v = p[lane + 32 * k];    // lanes consecutive -> coalesced
        part[k >> 1] += v.x + v.y + v.z + v.w;
    }
#pragma unroll
    for (int c = 0; c < 4; c++) {
        float v = part[c];
#pragma unroll
        for (int off = 16; off; off >>= 1) v += __shfl_xor_sync(0xffffffffu, v, off);
        if (lane == 0) s_ch[4 * w + c] = v * (1.0f / HW);
    }
    __syncthreads();

    if (w == 0) {
        // lanes 0..15 = experts; lanes 16..31 inert with -inf logits
        float l = -INFINITY;
        if (lane < E_EXP) {
            float acc = bg[lane];
#pragma unroll
            for (int c = 0; c < C_DIM; c++) acc += s_ch[c] * s_w[c * E_EXP + lane];
            l = acc;
        }
        // warp max
        float mx = l;
#pragma unroll
        for (int off = 16; off; off >>= 1) mx = fmaxf(mx, __shfl_xor_sync(0xffffffffu, mx, off));
        float e = __expf(l - mx);            // lanes>=16: exp(-inf)=0
        if (lane >= E_EXP) e = 0.f;
        float s = e;
#pragma unroll
        for (int off = 16; off; off >>= 1) s += __shfl_xor_sync(0xffffffffu, s, off);
        float prob = e / s;
        float lse  = mx + __logf(s);

        unsigned bal = __ballot_sync(0xffffffffu, l == mx);
        int arg = __ffs(bal) - 1;            // first (lowest-index) max, matches jnp argmax
        float gate = __shfl_sync(0xffffffffu, prob, arg);

        if (lane < E_EXP) atomicAdd(&g_sump[lane], prob);
        if (lane == 0) {
            g_gate[n] = gate;
            g_arg[n]  = arg;
            atomicAdd(&g_cnt[arg], 1.0f);
            atomicAdd(&g_zsum, lse);
        }
    }
}

// ---------------- kernel 3: capacity positions (single warp scan) ----------
__global__ void k_scan() {
    __shared__ int cnt[E_EXP];
    const int lane = threadIdx.x;
    if (lane < E_EXP) cnt[lane] = 0;
    __syncwarp();

    int nxt = g_arg[lane];                      // prefetch chunk 0
    for (int base = 0; base < N_TOK; base += 32) {
        int a = nxt;
        if (base + 32 < N_TOK) nxt = g_arg[base + 32 + lane];
        unsigned m   = __match_any_sync(0xffffffffu, a);
        int prior    = cnt[a];
        __syncwarp();                           // all reads before leader write
        int leader   = __ffs(m) - 1;
        if (lane == leader) cnt[a] = prior + __popc(m);
        g_pos[base + lane] = prior + __popc(m & ((1u << lane) - 1u));
        __syncwarp();
    }
}

// ---------------- kernel 4: scatter nonzeros + scalars ---------------------
__global__ void k_scatter(float* __restrict__ out) {
    int n = blockIdx.x * blockDim.x + threadIdx.x;
    if (n < N_TOK) {
        int pos = g_pos[n];
        if (pos < CCAP) {
            long long off = (long long)n * PLANE + (long long)g_arg[n] * CCAP + pos;
            out[off]        = 1.0f;        // dispatch (bool -> 1.0)
            out[HALF + off] = g_gate[n];   // combine
        }
    }
    if (blockIdx.x == 0 && threadIdx.x == 0) {
        float aux = 0.f;
#pragma unroll
        for (int e = 0; e < E_EXP; e++) aux += g_cnt[e] * g_sump[e];
        const float invN = 1.0f / (float)N_TOK;
        out[2 * HALF]     = g_zsum * invN;                         // z_loss
        out[2 * HALF + 1] = aux * (float)E_EXP * invN * invN;      // aux_loss
    }
}

// ---------------- launch ----------------------------------------------------
extern "C" void kernel_launch(void* const* d_in, const int* in_sizes, int n_in,
                              void* d_out, int out_size) {
    const float* X  = (const float*)d_in[0];
    const float* Wg = (const float*)d_in[1];
    const float* bg = (const float*)d_in[2];
    float* out = (float*)d_out;

    const long long n4 = (2LL * HALF) / 4;   // 12,582,912 float4 (divisible)

    k_zero<<<2048, 256>>>(out, n4);
    k_pool<<<N_TOK, 512>>>(X, Wg, bg);
    k_scan<<<1, 32>>>();
    k_scatter<<<(N_TOK + 255) / 256, 256>>>(out);
}

// round 2
// speedup vs baseline: 1.3728x; 1.3728x over previous
#include <cuda_runtime.h>
#include <cstdint>

#define N_TOK   4096
#define C_DIM   64
#define HW      256
#define E_EXP   16
#define CCAP    384
#define PLANE   (E_EXP * CCAP)             /* 6144 */
#define HALF    ((long long)N_TOK * PLANE) /* 25,165,824 */

// ---------------- device scratch ----------------
__device__ float g_gate[N_TOK];
__device__ int   g_arg[N_TOK];
__device__ float g_lse[N_TOK];
__device__ float g_prob[N_TOK * E_EXP];

// =====================================================================
// K1: fused zero-fill (1/3 of blocks) + pool/gate/softmax (2/3 of blocks)
// grid = 6144 blocks x 512 threads. bid%3==0 -> zero block, else pool.
// =====================================================================
__global__ void __launch_bounds__(512)
k_fused(const float* __restrict__ X, const float* __restrict__ Wg,
        const float* __restrict__ bg, float* __restrict__ out) {
    const int bid = blockIdx.x;
    const int tid = threadIdx.x;

    if (bid % 3 == 0) {
        // ---- zero block: z in [0, 2048), each zeroes 6144 float4 ----
        const long long z = bid / 3;
        float4* o4 = reinterpret_cast<float4*>(out) + z * 6144;
        const float4 zv = make_float4(0.f, 0.f, 0.f, 0.f);
#pragma unroll
        for (int i = 0; i < 12; i++) o4[i * 512 + tid] = zv;
        return;
    }

    // ---- pool block: token n in [0, 4096) ----
    const int n = bid - bid / 3 - 1;
    const int w    = tid >> 5;
    const int lane = tid & 31;

    __shared__ float s_ch[C_DIM];
    __shared__ float s_w[C_DIM * E_EXP];

    for (int i = tid; i < C_DIM * E_EXP; i += 512) s_w[i] = Wg[i];

    // coalesced read of this token's 16384 floats as float4
    const float4* p = reinterpret_cast<const float4*>(X + (size_t)n * C_DIM * HW)
                      + w * 256;                    // warp w owns channels [4w,4w+4)
    float part[4] = {0.f, 0.f, 0.f, 0.f};
#pragma unroll
    for (int k = 0; k < 8; k++) {
        float4 v = p[lane + 32 * k];                // lanes consecutive -> coalesced
        part[k >> 1] += v.x + v.y + v.z + v.w;
    }
#pragma unroll
    for (int c = 0; c < 4; c++) {
        float v = part[c];
#pragma unroll
        for (int off = 16; off; off >>= 1) v += __shfl_xor_sync(0xffffffffu, v, off);
        if (lane == 0) s_ch[4 * w + c] = v * (1.0f / HW);
    }
    __syncthreads();

    if (w == 0) {
        float l = -INFINITY;
        if (lane < E_EXP) {
            float acc = bg[lane];
#pragma unroll
            for (int c = 0; c < C_DIM; c++) acc += s_ch[c] * s_w[c * E_EXP + lane];
            l = acc;
        }
        float mx = l;
#pragma unroll
        for (int off = 16; off; off >>= 1) mx = fmaxf(mx, __shfl_xor_sync(0xffffffffu, mx, off));
        float e = (lane < E_EXP) ? __expf(l - mx) : 0.f;
        float s = e;
#pragma unroll
        for (int off = 16; off; off >>= 1) s += __shfl_xor_sync(0xffffffffu, s, off);
        float prob = e / s;
        float lse  = mx + __logf(s);

        unsigned bal = __ballot_sync(0xffffffffu, l == mx);
        int arg = __ffs(bal) - 1;                   // lowest-index max == jnp argmax
        float gate = __shfl_sync(0xffffffffu, prob, arg);

        if (lane < E_EXP) g_prob[n * E_EXP + lane] = prob;
        if (lane == 0) { g_gate[n] = gate; g_arg[n] = arg; g_lse[n] = lse; }
    }
}

// =====================================================================
// K2: parallel capacity scan + scatter + loss reductions. 1 block x 1024.
// =====================================================================
__global__ void __launch_bounds__(1024)
k_finish(float* __restrict__ out) {
    __shared__ unsigned short s_rank[N_TOK];   // within-chunk rank
    __shared__ unsigned char  s_argc[N_TOK];
    __shared__ int   s_cnt[32][E_EXP + 1];     // per-chunk histograms (padded)
    __shared__ int   s_off[32][E_EXP + 1];     // exclusive chunk prefix
    __shared__ int   s_tot[E_EXP];             // total argmax counts (pre-capacity)
    __shared__ float s_red[32];
    __shared__ float s_psum[E_EXP];

    const int tid  = threadIdx.x;
    const int w    = tid >> 5;   // 32 warps; warp w handles tokens [128w, 128w+128)
    const int lane = tid & 31;

    // ---- phase A: per-chunk expert ranks ----
    if (lane < E_EXP) s_cnt[w][lane] = 0;
    __syncwarp();
#pragma unroll
    for (int g = 0; g < 4; g++) {
        int n = 128 * w + 32 * g + lane;
        int a = g_arg[n];
        unsigned m = __match_any_sync(0xffffffffu, a);
        int prior = s_cnt[w][a];
        __syncwarp();
        if (lane == __ffs(m) - 1) s_cnt[w][a] = prior + __popc(m);
        s_rank[n] = (unsigned short)(prior + __popc(m & ((1u << lane) - 1u)));
        s_argc[n] = (unsigned char)a;
        __syncwarp();
    }
    __syncthreads();

    // ---- phase B: exclusive prefix over chunks (warp e scans 32 chunks) ----
    if (w < E_EXP) {
        int v = s_cnt[lane][w];
        int x = v;
#pragma unroll
        for (int off = 1; off < 32; off <<= 1) {
            int y = __shfl_up_sync(0xffffffffu, x, off);
            if (lane >= off) x += y;
        }
        s_off[lane][w] = x - v;
        if (lane == 31) s_tot[w] = x;
    }
    if (tid < E_EXP) s_psum[tid] = 0.f;
    __syncthreads();

    // ---- phase C: positions + scatter nonzeros ----
#pragma unroll
    for (int rep = 0; rep < 4; rep++) {
        int n = tid + rep * 1024;
        int a = s_argc[n];
        int pos = s_off[n >> 7][a] + (int)s_rank[n];
        if (pos < CCAP) {
            long long off = (long long)n * PLANE + a * CCAP + pos;
            out[off]        = 1.0f;         // dispatch
            out[HALF + off] = g_gate[n];    // combine
        }
    }

    // ---- phase D: z_loss (mean lse) ----
    float z = 0.f;
#pragma unroll
    for (int rep = 0; rep < 4; rep++) z += g_lse[tid + rep * 1024];
#pragma unroll
    for (int off = 16; off; off >>= 1) z += __shfl_xor_sync(0xffffffffu, z, off);
    if (lane == 0) s_red[w] = z;
    __syncthreads();
    if (w == 0) {
        float v = s_red[lane];
#pragma unroll
        for (int off = 16; off; off >>= 1) v += __shfl_xor_sync(0xffffffffu, v, off);
        if (lane == 0) out[2 * HALF] = v * (1.0f / (float)N_TOK);
    }

    // ---- phase E: aux loss. thread (grp=tid>>4, e=tid&15) sums 64 tokens ----
    {
        int e = tid & 15, grp = tid >> 4;
        float s = 0.f;
#pragma unroll
        for (int r = 0; r < 64; r++) s += g_prob[(grp + r * 64) * E_EXP + e];
        atomicAdd(&s_psum[e], s);
        __syncthreads();
        if (tid == 0) {
            float aux = 0.f;
#pragma unroll
            for (int e2 = 0; e2 < E_EXP; e2++) aux += s_psum[e2] * (float)s_tot[e2];
            const float invN = 1.0f / (float)N_TOK;
            out[2 * HALF + 1] = aux * (float)E_EXP * invN * invN;
        }
    }
}

// ---------------- launch ----------------
extern "C" void kernel_launch(void* const* d_in, const int* in_sizes, int n_in,
                              void* d_out, int out_size) {
    const float* X  = (const float*)d_in[0];
    const float* Wg = (const float*)d_in[1];
    const float* bg = (const float*)d_in[2];
    float* out = (float*)d_out;

    k_fused<<<6144, 512>>>(X, Wg, bg, out);
    k_finish<<<1, 1024>>>(out);
}

// round 3
// speedup vs baseline: 1.4045x; 1.0230x over previous
#include <cuda_runtime.h>
#include <cstdint>

#define N_TOK   4096
#define C_DIM   64
#define HW      256
#define E_EXP   16
#define CCAP    384
#define PLANE   (E_EXP * CCAP)             /* 6144 */
#define HALF    ((long long)N_TOK * PLANE) /* 25,165,824 */
#define NWORK   6144                        /* 2048 zero + 4096 pool blocks */

// ---------------- device scratch (persistent; reset each run by finish block) ----
__device__ float g_gate[N_TOK];
__device__ int   g_arg[N_TOK];
__device__ float g_psum[E_EXP];   // sum of probs per expert (atomic)
__device__ float g_zsum;          // sum of logsumexp (atomic)
__device__ int   g_ctr;           // completed work blocks

// =====================================================================
// Single fused kernel. grid = 6145 x 512.
//   bid % 3 == 0 (bid<6144) : zero 1/3  -> streams the 201MB of zeros
//   else        (bid<6144)  : pool 2/3  -> streams the 268MB of X
//   bid == 6144             : finish    -> waits, scans, scatters, scalars
// =====================================================================
__global__ void __launch_bounds__(512)
k_all(const float* __restrict__ X, const float* __restrict__ Wg,
      const float* __restrict__ bg, float* __restrict__ out) {
    const int bid = blockIdx.x;
    const int tid = threadIdx.x;
    const int w    = tid >> 5;
    const int lane = tid & 31;

    if (bid < NWORK && bid % 3 == 0) {
        // ---------------- zero block: z in [0, 2048) ----------------
        const long long z = bid / 3;
        float4* o4 = reinterpret_cast<float4*>(out) + z * 6144;
        const float4 zv = make_float4(0.f, 0.f, 0.f, 0.f);
#pragma unroll
        for (int i = 0; i < 12; i++) o4[i * 512 + tid] = zv;
        __syncthreads();
        if (tid == 0) { __threadfence(); atomicAdd(&g_ctr, 1); }
        return;
    }

    if (bid < NWORK) {
        // ---------------- pool block: token n in [0, 4096) ----------------
        const int n = bid - bid / 3 - 1;

        __shared__ float s_ch[C_DIM];
        __shared__ float s_w[C_DIM * E_EXP];

        for (int i = tid; i < C_DIM * E_EXP; i += 512) s_w[i] = Wg[i];

        // coalesced read of this token's 16384 floats as float4
        const float4* p = reinterpret_cast<const float4*>(X + (size_t)n * C_DIM * HW)
                          + w * 256;                // warp w owns channels [4w,4w+4)
        float part[4] = {0.f, 0.f, 0.f, 0.f};
#pragma unroll
        for (int k = 0; k < 8; k++) {
            float4 v = p[lane + 32 * k];            // lanes consecutive -> coalesced
            part[k >> 1] += v.x + v.y + v.z + v.w;
        }
#pragma unroll
        for (int c = 0; c < 4; c++) {
            float v = part[c];
#pragma unroll
            for (int off = 16; off; off >>= 1) v += __shfl_xor_sync(0xffffffffu, v, off);
            if (lane == 0) s_ch[4 * w + c] = v * (1.0f / HW);
        }
        __syncthreads();

        if (w == 0) {
            float l = -INFINITY;
            if (lane < E_EXP) {
                float acc = bg[lane];
#pragma unroll
                for (int c = 0; c < C_DIM; c++) acc += s_ch[c] * s_w[c * E_EXP + lane];
                l = acc;
            }
            float mx = l;
#pragma unroll
            for (int off = 16; off; off >>= 1) mx = fmaxf(mx, __shfl_xor_sync(0xffffffffu, mx, off));
            float e = (lane < E_EXP) ? __expf(l - mx) : 0.f;
            float s = e;
#pragma unroll
            for (int off = 16; off; off >>= 1) s += __shfl_xor_sync(0xffffffffu, s, off);
            float prob = e / s;
            float lse  = mx + __logf(s);

            unsigned bal = __ballot_sync(0xffffffffu, l == mx);
            int arg = __ffs(bal) - 1;               // lowest-index max == jnp argmax
            float gate = __shfl_sync(0xffffffffu, prob, arg);

            if (lane < E_EXP) atomicAdd(&g_psum[lane], prob);
            if (lane == 0) {
                g_gate[n] = gate;
                g_arg[n]  = arg;
                atomicAdd(&g_zsum, lse);
                __threadfence();
                atomicAdd(&g_ctr, 1);
            }
        }
        return;
    }

    // ---------------- finish block (bid == 6144) ----------------
    __shared__ unsigned short s_rank[N_TOK];
    __shared__ unsigned char  s_argc[N_TOK];
    __shared__ int s_cnt[16][E_EXP + 1];   // per-chunk histograms (chunk = 256 tokens)
    __shared__ int s_off[16][E_EXP + 1];   // exclusive prefix per chunk
    __shared__ int s_tot[E_EXP];

    // wait for all work blocks
    if (tid == 0) {
        while (atomicAdd(&g_ctr, 0) < NWORK) __nanosleep(64);
        __threadfence();
    }
    __syncthreads();

    // ---- phase A: per-chunk expert ranks. warp w owns tokens [256w, 256w+256) ----
    if (lane <= E_EXP) s_cnt[w][lane] = 0;
    __syncwarp();
#pragma unroll
    for (int g = 0; g < 8; g++) {
        int n = 256 * w + 32 * g + lane;
        int a = g_arg[n];
        unsigned m = __match_any_sync(0xffffffffu, a);
        int prior = s_cnt[w][a];
        __syncwarp();
        if (lane == (int)__ffs(m) - 1) s_cnt[w][a] = prior + __popc(m);
        s_rank[n] = (unsigned short)(prior + __popc(m & ((1u << lane) - 1u)));
        s_argc[n] = (unsigned char)a;
        __syncwarp();
    }
    __syncthreads();

    // ---- phase B: exclusive prefix over 16 chunks; warp w<16 handles expert w ----
    if (w < E_EXP && lane < 16) {
        int v = s_cnt[lane][w];
        int x = v;
#pragma unroll
        for (int off = 1; off < 16; off <<= 1) {
            int y = __shfl_up_sync(0x0000ffffu, x, off);
            if (lane >= off) x += y;
        }
        s_off[lane][w] = x - v;
        if (lane == 15) s_tot[w] = x;
    }
    __syncthreads();

    // ---- phase C: positions + scatter nonzeros ----
#pragma unroll
    for (int rep = 0; rep < 8; rep++) {
        int n = tid + rep * 512;
        int a = s_argc[n];
        int pos = s_off[n >> 8][a] + (int)s_rank[n];
        if (pos < CCAP) {
            long long off = (long long)n * PLANE + a * CCAP + pos;
            out[off]        = 1.0f;          // dispatch
            out[HALF + off] = g_gate[n];     // combine
        }
    }

    // ---- scalars + state reset for next replay ----
    if (tid == 0) {
        float aux = 0.f;
#pragma unroll
        for (int e = 0; e < E_EXP; e++) aux += g_psum[e] * (float)s_tot[e];
        const float invN = 1.0f / (float)N_TOK;
        out[2 * HALF]     = g_zsum * invN;                        // z_loss
        out[2 * HALF + 1] = aux * (float)E_EXP * invN * invN;     // aux_loss
        // reset persistent state so every graph replay is identical
        g_zsum = 0.f;
#pragma unroll
        for (int e = 0; e < E_EXP; e++) g_psum[e] = 0.f;
        __threadfence();
        g_ctr = 0;
    }
}

// ---------------- launch ----------------
extern "C" void kernel_launch(void* const* d_in, const int* in_sizes, int n_in,
                              void* d_out, int out_size) {
    const float* X  = (const float*)d_in[0];
    const float* Wg = (const float*)d_in[1];
    const float* bg = (const float*)d_in[2];
    float* out = (float*)d_out;

    k_all<<<NWORK + 1, 512>>>(X, Wg, bg, out);
}